// round 15
// baseline (speedup 1.0000x reference)
#include <cuda_runtime.h>

// Guided filter, fully fused, SMEM-free warp-sliding, 2 columns per lane.
// R14 (68.7us) pushed one residency tier: __launch_bounds__(128,9) pins regs
// to 56 -> 36 warps/SM cap; CHUNKS=12 x CH=88 supplies 5184 warps (35.0/SM),
// 1296 blocks <= 1332 capacity (single wave). Trip count 84 = 28*3 keeps the
// clean unrolled codegen. Last chunk anchored at r0=936 (benign overlap).

#define W 1024
#define H 1024
#define EPS81 8.1e-5f           // 81 * 1e-6
#define C9 (1.0f / 9.0f)

#define OUTC 60
#define BANDS 18                // ceil(1024/60)
#define CH 88                   // uniform chunk height
#define CHUNKS 12
#define WPB 4                   // 128 threads
#define UNITS (24 * BANDS * CHUNKS)        // 5184 warps
#define NBLOCKS (UNITS / WPB)              // 1296 blocks

__global__ __launch_bounds__(128, 9) void gf_kernel(const float* __restrict__ x,
                                                    const float* __restrict__ y,
                                                    float* __restrict__ out)
{
    const int wid  = threadIdx.x >> 5;
    const int lane = threadIdx.x & 31;
    const int g    = blockIdx.x * WPB + wid;

    const int plane = g / (BANDS * CHUNKS);
    const int rem   = g - plane * (BANDS * CHUNKS);
    const int band  = rem / CHUNKS;
    const int chunk = rem - band * CHUNKS;

    const int cfirst = band * OUTC - 2 + lane * 2;   // this lane's 2 columns
    const int cl     = min(max(cfirst, 0), W - 2);   // clamped aligned load col
    const int r0     = min(chunk * CH, H - CH);      // last chunk anchored at 936

    const bool dupL = (cfirst < 0);       // lane left of image: both elems = col 0
    const bool dupR = (cfirst >= W);      // lane right of image: both elems = col W-1
    const bool pl   = (cfirst == 0);      // elem .x is image col 0
    const bool pr   = (cfirst == W - 2);  // elem .y is image col 1023
    const bool do_store = (lane >= 1) && (lane <= 30) && (cfirst < W);

    const size_t pb = (size_t)plane * (size_t)(W * H);
    const float* __restrict__ px = x + pb + cl;
    const float* __restrict__ py = y + pb + cl;
    float* po = out + pb + (size_t)r0 * W + cfirst;

    // load + column-replication fixup
#define LD2(v, P, row) { \
    v = *reinterpret_cast<const float2*>((P) + (size_t)(row) * W); \
    if (dupL) v.y = v.x; \
    if (dupR) v.x = v.y; }
#define LDP(v, PTR) { \
    v = *reinterpret_cast<const float2*>(PTR); \
    if (dupL) v.y = v.x; \
    if (dupR) v.x = v.y; }

    // Horizontal 3-sums for a float2 pair: 4 shuffles total.
#define HQ2(xv, yv, HX, HY, HXY, HXX) { \
    float xl = __shfl_up_sync(0xffffffffu, xv.y, 1); \
    float xr = __shfl_down_sync(0xffffffffu, xv.x, 1); \
    float yl = __shfl_up_sync(0xffffffffu, yv.y, 1); \
    float yr = __shfl_down_sync(0xffffffffu, yv.x, 1); \
    float mx = xv.x + xv.y; \
    float my = yv.x + yv.y; \
    HX.x = xl + mx;  HX.y = mx + xr; \
    HY.x = yl + my;  HY.y = my + yr; \
    float mxy = fmaf(xv.x, yv.x, xv.y * yv.y); \
    float mxx = fmaf(xv.x, xv.x, xv.y * xv.y); \
    HXY.x = fmaf(xl, yl, mxy);  HXY.y = fmaf(xr, yr, mxy); \
    HXX.x = fmaf(xl, xl, mxx);  HXX.y = fmaf(xr, xr, mxx); }

    // A,b9 per element + horizontal 3-sum with col replication: 4 shuffles.
#define ABROW2(Sx, Sy, Sxy, Sxx, HA, HB) { \
    float2 A, B; \
    { float t = Sx.x * Sy.x; \
      float num = fmaf(Sxy.x, 9.0f, -t); \
      float u   = fmaf(-Sx.x, Sx.x, EPS81); \
      float den = fmaf(Sxx.x, 9.0f, u); \
      A.x = __fdividef(num, den); \
      B.x = fmaf(-A.x, Sx.x, Sy.x); } \
    { float t = Sx.y * Sy.y; \
      float num = fmaf(Sxy.y, 9.0f, -t); \
      float u   = fmaf(-Sx.y, Sx.y, EPS81); \
      float den = fmaf(Sxx.y, 9.0f, u); \
      A.y = __fdividef(num, den); \
      B.y = fmaf(-A.y, Sx.y, Sy.y); } \
    float Al = __shfl_up_sync(0xffffffffu, A.y, 1); \
    float Ar = __shfl_down_sync(0xffffffffu, A.x, 1); \
    float Bl = __shfl_up_sync(0xffffffffu, B.y, 1); \
    float Br = __shfl_down_sync(0xffffffffu, B.x, 1); \
    if (pl) { Al = A.x;  Bl = B.x; } \
    if (pr) { Ar = A.y;  Br = B.y; } \
    float ma = A.x + A.y, mb = B.x + B.y; \
    HA.x = Al + ma;  HA.y = ma + Ar; \
    HB.x = Bl + mb;  HB.y = mb + Br; }

#define ADD2(r, a, b) { r.x = a.x + b.x;  r.y = a.y + b.y; }

    // Sliding-sum state (invariant at top of step for output row rr):
    //   hp* = h at input row rr+1,  P* = h[rr] + h[rr+1]
    //   hAp = hA at A-row rr,       PA = hA[rr-1] + hA[rr]   (B likewise)
    //   xc0 = x[rr], xc1 = x[rr+1]; (nxv,nyv) = input row min(rr+2,H-1)
    float2 hpx, hpy, hpxy, hpxx, Px, Py, Pxy, Pxx;
    float2 hAp, hBp, PA, PB;
    float2 xc0, xc1, nxv, nyv;

    // ---------------- prologue ----------------
    {
        float2 t0x, t0y, t0xy, t0xx, t1x, t1y, t1xy, t1xx;
        float2 h0x, h0y, h0xy, h0xx, h1x, h1y, h1xy, h1xx;
        float2 xv, yv;
        LD2(xv, px, max(r0 - 2, 0))  LD2(yv, py, max(r0 - 2, 0))
        HQ2(xv, yv, t0x, t0y, t0xy, t0xx)
        LD2(xv, px, max(r0 - 1, 0))  LD2(yv, py, max(r0 - 1, 0))
        HQ2(xv, yv, t1x, t1y, t1xy, t1xx)
        LD2(xv, px, r0)              LD2(yv, py, r0)
        HQ2(xv, yv, h0x, h0y, h0xy, h0xx)  xc0 = xv;
        LD2(xv, px, r0 + 1)          LD2(yv, py, r0 + 1)
        HQ2(xv, yv, h1x, h1y, h1xy, h1xx)  xc1 = xv;

        float2 Sx, Sy, Sxy, Sxx, hAm, hBm, hA0, hB0;
        Sx.x = t0x.x + t1x.x + h0x.x;    Sx.y = t0x.y + t1x.y + h0x.y;
        Sy.x = t0y.x + t1y.x + h0y.x;    Sy.y = t0y.y + t1y.y + h0y.y;
        Sxy.x = t0xy.x + t1xy.x + h0xy.x; Sxy.y = t0xy.y + t1xy.y + h0xy.y;
        Sxx.x = t0xx.x + t1xx.x + h0xx.x; Sxx.y = t0xx.y + t1xx.y + h0xx.y;
        ABROW2(Sx, Sy, Sxy, Sxx, hAm, hBm)                 // A row r0-1
        Sx.x = t1x.x + h0x.x + h1x.x;    Sx.y = t1x.y + h0x.y + h1x.y;
        Sy.x = t1y.x + h0y.x + h1y.x;    Sy.y = t1y.y + h0y.y + h1y.y;
        Sxy.x = t1xy.x + h0xy.x + h1xy.x; Sxy.y = t1xy.y + h0xy.y + h1xy.y;
        Sxx.x = t1xx.x + h0xx.x + h1xx.x; Sxx.y = t1xx.y + h0xx.y + h1xx.y;
        ABROW2(Sx, Sy, Sxy, Sxx, hA0, hB0)                 // A row r0
        if (r0 == 0) { hAm = hA0;  hBm = hB0; }            // top: A(-1) := A(0)

        hpx = h1x;  hpy = h1y;  hpxy = h1xy;  hpxx = h1xx;
        ADD2(Px, h0x, h1x)    ADD2(Py, h0y, h1y)
        ADD2(Pxy, h0xy, h1xy) ADD2(Pxx, h0xx, h1xx)
        hAp = hA0;  hBp = hB0;
        ADD2(PA, hAm, hA0)    ADD2(PB, hBm, hB0)
    }

    const float* pxr = px + (size_t)(r0 + 3) * W;  // r0+3 <= 939, always valid
    const float* pyr = py + (size_t)(r0 + 3) * W;
    LD2(nxv, px, r0 + 2)
    LD2(nyv, py, r0 + 2)

    // Core of one step (input row rr+2 in xv/yv).
#define SCORE(xv, yv) \
    float2 nx_, ny_, nxy_, nxx_; \
    HQ2(xv, yv, nx_, ny_, nxy_, nxx_) \
    float2 Sx, Sy, Sxy, Sxx; \
    ADD2(Sx, Px, nx_)   ADD2(Sy, Py, ny_) \
    ADD2(Sxy, Pxy, nxy_) ADD2(Sxx, Pxx, nxx_) \
    ADD2(Px, hpx, nx_)  ADD2(Py, hpy, ny_) \
    ADD2(Pxy, hpxy, nxy_) ADD2(Pxx, hpxx, nxx_) \
    hpx = nx_;  hpy = ny_;  hpxy = nxy_;  hpxx = nxx_; \
    float2 hAn, hBn; \
    ABROW2(Sx, Sy, Sxy, Sxx, hAn, hBn)

#define STAIL(xv) \
    float2 SA, SB; \
    ADD2(SA, PA, hAn)  ADD2(SB, PB, hBn) \
    ADD2(PA, hAp, hAn) ADD2(PB, hBp, hBn) \
    hAp = hAn;  hBp = hBn; \
    float2 res; \
    res.x = fminf(fmaxf(truncf(fmaf(SA.x, xc0.x, SB.x * C9) * C9), 0.0f), 255.0f); \
    res.y = fminf(fmaxf(truncf(fmaf(SA.y, xc0.y, SB.y * C9) * C9), 0.0f), 255.0f); \
    if (do_store) *reinterpret_cast<float2*>(po) = res; \
    po += W; \
    xc0 = xc1;  xc1 = xv;

    // Guard-free steps i = 0..83 (84 = 28*3 iterations, compile-time constant).
    // Safe: max rr = r0+83 -> rr+3 = r0+86 <= 1022 for every chunk (r0 <= 936).
#pragma unroll 3
    for (int i = 0; i < CH - 4; ++i) {
        float2 xv = nxv, yv = nyv;
        LDP(nxv, pxr)  LDP(nyv, pyr)
        pxr += W;  pyr += W;
        SCORE(xv, yv)
        STAIL(xv)
    }

    // Guarded steps: last 4 rows of the chunk (bottom replication only fires
    // for the r0 == 936 chunk; plain steps otherwise).
    const int rbase = r0 + CH - 4;
#define STEP_G(k) { \
        const int rr = rbase + (k); \
        float2 xv = nxv, yv = nyv; \
        LDP(nxv, pxr)  LDP(nyv, pyr) \
        if (rr + 4 < H) { pxr += W;  pyr += W; } \
        SCORE(xv, yv) \
        if (rr + 1 >= H) { hAn = hAp;  hBn = hBp; }   /* A(H) := A(H-1) */ \
        STAIL(xv) }

    STEP_G(0)
    STEP_G(1)
    STEP_G(2)
    STEP_G(3)
#undef STEP_G
#undef STAIL
#undef SCORE
#undef ADD2
#undef ABROW2
#undef HQ2
#undef LDP
#undef LD2
}

extern "C" void kernel_launch(void* const* d_in, const int* in_sizes, int n_in,
                              void* d_out, int out_size) {
    const float* x = (const float*)d_in[0];
    const float* y = (const float*)d_in[1];
    float* out     = (float*)d_out;

    gf_kernel<<<NBLOCKS, 32 * WPB>>>(x, y, out);
}

// round 16
// speedup vs baseline: 1.2482x; 1.2482x over previous
#include <cuda_runtime.h>

// Guided filter, fully fused, SMEM-free warp-sliding, 2 columns per lane.
// R14 config (68.7us: CHUNKS=11 x CH=94, 128 thr, launch_bounds(128,8)) with
// the pairwise arithmetic converted to Blackwell packed f32x2 (FFMA2/FADD2
// via PTX fma/add/mul.rn.f32x2 -- ptxas never emits these from plain C++).
// Scalar ops remain only where lane-crossing or per-element HW forces them:
// shuffles, rcp.approx, trunc/min/max.

#define W 1024
#define H 1024
#define EPS81 8.1e-5f           // 81 * 1e-6
#define C9 (1.0f / 9.0f)

#define OUTC 60
#define BANDS 18                // ceil(1024/60)
#define CH 94                   // uniform chunk height
#define CHUNKS 11
#define WPB 4                   // 128 threads
#define UNITS (24 * BANDS * CHUNKS)        // 4752 warps
#define NBLOCKS (UNITS / WPB)              // 1188 blocks

typedef unsigned long long ull;

__device__ __forceinline__ ull pk(float a, float b) {
    ull r; asm("mov.b64 %0, {%1, %2};" : "=l"(r) : "f"(a), "f"(b)); return r;
}
__device__ __forceinline__ void upk(ull v, float& a, float& b) {
    asm("mov.b64 {%0, %1}, %2;" : "=f"(a), "=f"(b) : "l"(v));
}
__device__ __forceinline__ ull addx(ull a, ull b) {
    ull r; asm("add.rn.f32x2 %0, %1, %2;" : "=l"(r) : "l"(a), "l"(b)); return r;
}
__device__ __forceinline__ ull mulx(ull a, ull b) {
    ull r; asm("mul.rn.f32x2 %0, %1, %2;" : "=l"(r) : "l"(a), "l"(b)); return r;
}
__device__ __forceinline__ ull fmax2p(ull a, ull b, ull c) {
    ull r; asm("fma.rn.f32x2 %0, %1, %2, %3;" : "=l"(r) : "l"(a), "l"(b), "l"(c)); return r;
}
__device__ __forceinline__ float rcpa(float v) {
    float r; asm("rcp.approx.f32 %0, %1;" : "=f"(r) : "f"(v)); return r;
}

__global__ __launch_bounds__(128, 8) void gf_kernel(const float* __restrict__ x,
                                                    const float* __restrict__ y,
                                                    float* __restrict__ out)
{
    const int wid  = threadIdx.x >> 5;
    const int lane = threadIdx.x & 31;
    const int g    = blockIdx.x * WPB + wid;

    const int plane = g / (BANDS * CHUNKS);
    const int rem   = g - plane * (BANDS * CHUNKS);
    const int band  = rem / CHUNKS;
    const int chunk = rem - band * CHUNKS;

    const int cfirst = band * OUTC - 2 + lane * 2;   // this lane's 2 columns
    const int cl     = min(max(cfirst, 0), W - 2);   // clamped aligned load col
    const int r0     = min(chunk * CH, H - CH);      // last chunk anchored at 930

    const bool dupL = (cfirst < 0);
    const bool dupR = (cfirst >= W);
    const bool pl   = (cfirst == 0);
    const bool pr   = (cfirst == W - 2);
    const bool do_store = (lane >= 1) && (lane <= 30) && (cfirst < W);

    const size_t pb = (size_t)plane * (size_t)(W * H);
    const float* __restrict__ px = x + pb + cl;
    const float* __restrict__ py = y + pb + cl;
    float* po = out + pb + (size_t)r0 * W + cfirst;

    // packed constants (built once; uniform across the warp)
    const ull NINE2 = pk(9.0f, 9.0f);
    const ull NEG12 = pk(-1.0f, -1.0f);
    const ull EPS2  = pk(EPS81, EPS81);
    const ull C92   = pk(C9, C9);

#define LD2(v, P, row) { \
    v = *reinterpret_cast<const float2*>((P) + (size_t)(row) * W); \
    if (dupL) v.y = v.x; \
    if (dupR) v.x = v.y; }
#define LDP(v, PTR) { \
    v = *reinterpret_cast<const float2*>(PTR); \
    if (dupL) v.y = v.x; \
    if (dupR) v.x = v.y; }

    // Scalar HQ for the prologue (as R14).
#define HQ2S(xv, yv, HX, HY, HXY, HXX) { \
    float xl = __shfl_up_sync(0xffffffffu, xv.y, 1); \
    float xr = __shfl_down_sync(0xffffffffu, xv.x, 1); \
    float yl = __shfl_up_sync(0xffffffffu, yv.y, 1); \
    float yr = __shfl_down_sync(0xffffffffu, yv.x, 1); \
    float mx = xv.x + xv.y; \
    float my = yv.x + yv.y; \
    HX.x = xl + mx;  HX.y = mx + xr; \
    HY.x = yl + my;  HY.y = my + yr; \
    float mxy = fmaf(xv.x, yv.x, xv.y * yv.y); \
    float mxx = fmaf(xv.x, xv.x, xv.y * xv.y); \
    HXY.x = fmaf(xl, yl, mxy);  HXY.y = fmaf(xr, yr, mxy); \
    HXX.x = fmaf(xl, xl, mxx);  HXX.y = fmaf(xr, xr, mxx); }

    // Scalar ABROW for the prologue (as R14), float2 in/out.
#define ABROW2S(Sx, Sy, Sxy, Sxx, HA, HB) { \
    float2 A, B; \
    { float t = Sx.x * Sy.x; \
      float num = fmaf(Sxy.x, 9.0f, -t); \
      float u   = fmaf(-Sx.x, Sx.x, EPS81); \
      float den = fmaf(Sxx.x, 9.0f, u); \
      A.x = num * rcpa(den); \
      B.x = fmaf(-A.x, Sx.x, Sy.x); } \
    { float t = Sx.y * Sy.y; \
      float num = fmaf(Sxy.y, 9.0f, -t); \
      float u   = fmaf(-Sx.y, Sx.y, EPS81); \
      float den = fmaf(Sxx.y, 9.0f, u); \
      A.y = num * rcpa(den); \
      B.y = fmaf(-A.y, Sx.y, Sy.y); } \
    float Al = __shfl_up_sync(0xffffffffu, A.y, 1); \
    float Ar = __shfl_down_sync(0xffffffffu, A.x, 1); \
    float Bl = __shfl_up_sync(0xffffffffu, B.y, 1); \
    float Br = __shfl_down_sync(0xffffffffu, B.x, 1); \
    if (pl) { Al = A.x;  Bl = B.x; } \
    if (pr) { Ar = A.y;  Br = B.y; } \
    float ma = A.x + A.y, mb = B.x + B.y; \
    HA.x = Al + ma;  HA.y = ma + Ar; \
    HB.x = Bl + mb;  HB.y = mb + Br; }

    // Packed sliding-sum state. Invariant at top of step for output row rr:
    //   hp* = h at input row rr+1,  P* = h[rr] + h[rr+1]   (packed pairs)
    //   hApp = hA at A-row rr,      PAp = hA[rr-1] + hA[rr] (B likewise)
    //   xc0p = x[rr], xc1p = x[rr+1] (packed); (nxv,nyv) = row min(rr+2,H-1)
    ull hpxp, hpyp, hpxyp, hpxxp, Pxp, Pyp, Pxyp, Pxxp;
    ull hApp, hBpp, PAp, PBp;
    ull xc0p, xc1p;
    float2 nxv, nyv;

    // ---------------- prologue (scalar, as R14; pack at the end) ----------------
    {
        float2 t0x, t0y, t0xy, t0xx, t1x, t1y, t1xy, t1xx;
        float2 h0x, h0y, h0xy, h0xx, h1x, h1y, h1xy, h1xx;
        float2 xv, yv;
        LD2(xv, px, max(r0 - 2, 0))  LD2(yv, py, max(r0 - 2, 0))
        HQ2S(xv, yv, t0x, t0y, t0xy, t0xx)
        LD2(xv, px, max(r0 - 1, 0))  LD2(yv, py, max(r0 - 1, 0))
        HQ2S(xv, yv, t1x, t1y, t1xy, t1xx)
        LD2(xv, px, r0)              LD2(yv, py, r0)
        HQ2S(xv, yv, h0x, h0y, h0xy, h0xx)
        xc0p = pk(xv.x, xv.y);
        LD2(xv, px, r0 + 1)          LD2(yv, py, r0 + 1)
        HQ2S(xv, yv, h1x, h1y, h1xy, h1xx)
        xc1p = pk(xv.x, xv.y);

        float2 Sx, Sy, Sxy, Sxx, hAm, hBm, hA0, hB0;
        Sx.x = t0x.x + t1x.x + h0x.x;    Sx.y = t0x.y + t1x.y + h0x.y;
        Sy.x = t0y.x + t1y.x + h0y.x;    Sy.y = t0y.y + t1y.y + h0y.y;
        Sxy.x = t0xy.x + t1xy.x + h0xy.x; Sxy.y = t0xy.y + t1xy.y + h0xy.y;
        Sxx.x = t0xx.x + t1xx.x + h0xx.x; Sxx.y = t0xx.y + t1xx.y + h0xx.y;
        ABROW2S(Sx, Sy, Sxy, Sxx, hAm, hBm)                // A row r0-1
        Sx.x = t1x.x + h0x.x + h1x.x;    Sx.y = t1x.y + h0x.y + h1x.y;
        Sy.x = t1y.x + h0y.x + h1y.x;    Sy.y = t1y.y + h0y.y + h1y.y;
        Sxy.x = t1xy.x + h0xy.x + h1xy.x; Sxy.y = t1xy.y + h0xy.y + h1xy.y;
        Sxx.x = t1xx.x + h0xx.x + h1xx.x; Sxx.y = t1xx.y + h0xx.y + h1xx.y;
        ABROW2S(Sx, Sy, Sxy, Sxx, hA0, hB0)                // A row r0
        if (r0 == 0) { hAm = hA0;  hBm = hB0; }            // top: A(-1) := A(0)

        hpxp  = pk(h1x.x, h1x.y);   hpyp  = pk(h1y.x, h1y.y);
        hpxyp = pk(h1xy.x, h1xy.y); hpxxp = pk(h1xx.x, h1xx.y);
        Pxp  = pk(h0x.x + h1x.x,   h0x.y + h1x.y);
        Pyp  = pk(h0y.x + h1y.x,   h0y.y + h1y.y);
        Pxyp = pk(h0xy.x + h1xy.x, h0xy.y + h1xy.y);
        Pxxp = pk(h0xx.x + h1xx.x, h0xx.y + h1xx.y);
        hApp = pk(hA0.x, hA0.y);    hBpp = pk(hB0.x, hB0.y);
        PAp  = pk(hAm.x + hA0.x, hAm.y + hA0.y);
        PBp  = pk(hBm.x + hB0.x, hBm.y + hB0.y);
    }

    const float* pxr = px + (size_t)(r0 + 3) * W;  // r0+3 <= 933, always valid
    const float* pyr = py + (size_t)(r0 + 3) * W;
    LD2(nxv, px, r0 + 2)
    LD2(nyv, py, r0 + 2)

    // Core of one step (input row rr+2 in xv/yv). Packed everywhere possible.
#define SCORE(xv, yv) \
    float xl = __shfl_up_sync(0xffffffffu, xv.y, 1); \
    float xr = __shfl_down_sync(0xffffffffu, xv.x, 1); \
    float yl = __shfl_up_sync(0xffffffffu, yv.y, 1); \
    float yr = __shfl_down_sync(0xffffffffu, yv.x, 1); \
    float mx = xv.x + xv.y, my = yv.x + yv.y; \
    float mxy = fmaf(xv.x, yv.x, xv.y * yv.y); \
    float mxx = fmaf(xv.x, xv.x, xv.y * xv.y); \
    ull nxp  = pk(xl + mx, mx + xr); \
    ull nyp  = pk(yl + my, my + yr); \
    ull nxyp = pk(fmaf(xl, yl, mxy), fmaf(xr, yr, mxy)); \
    ull nxxp = pk(fmaf(xl, xl, mxx), fmaf(xr, xr, mxx)); \
    ull Sxp  = addx(Pxp,  nxp);   Pxp  = addx(hpxp,  nxp);   hpxp  = nxp; \
    ull Syp  = addx(Pyp,  nyp);   Pyp  = addx(hpyp,  nyp);   hpyp  = nyp; \
    ull Sxyp = addx(Pxyp, nxyp);  Pxyp = addx(hpxyp, nxyp);  hpxyp = nxyp; \
    ull Sxxp = addx(Pxxp, nxxp);  Pxxp = addx(hpxxp, nxxp);  hpxxp = nxxp; \
    /* packed A,b9 */ \
    ull t9  = mulx(Sxyp, NINE2); \
    ull nSy = mulx(Syp, NEG12); \
    ull num = fmax2p(Sxp, nSy, t9);        /* 9Sxy - Sx*Sy */ \
    ull nSx = mulx(Sxp, NEG12); \
    ull uu  = fmax2p(nSx, Sxp, EPS2);      /* 81eps - Sx^2 */ \
    ull den = fmax2p(Sxxp, NINE2, uu);     /* 9Sxx - Sx^2 + 81eps */ \
    float d0, d1; upk(den, d0, d1); \
    ull rcp2 = pk(rcpa(d0), rcpa(d1)); \
    ull Ap = mulx(num, rcp2); \
    ull Bp = fmax2p(Ap, nSx, Syp);         /* Sy - A*Sx */ \
    float a0, a1, b0, b1; \
    upk(Ap, a0, a1);  upk(Bp, b0, b1); \
    float Al = __shfl_up_sync(0xffffffffu, a1, 1); \
    float Ar = __shfl_down_sync(0xffffffffu, a0, 1); \
    float Bl = __shfl_up_sync(0xffffffffu, b1, 1); \
    float Br = __shfl_down_sync(0xffffffffu, b0, 1); \
    if (pl) { Al = a0;  Bl = b0; } \
    if (pr) { Ar = a1;  Br = b1; } \
    float ma = a0 + a1, mb = b0 + b1; \
    ull hAn = pk(Al + ma, ma + Ar); \
    ull hBn = pk(Bl + mb, mb + Br);

#define STAIL(xv) \
    ull SAp = addx(PAp, hAn);  ull SBp = addx(PBp, hBn); \
    PAp = addx(hApp, hAn);     PBp = addx(hBpp, hBn); \
    hApp = hAn;  hBpp = hBn; \
    ull sbc = mulx(SBp, C92); \
    ull rp  = mulx(fmax2p(SAp, xc0p, sbc), C92); \
    float r0f, r1f; upk(rp, r0f, r1f); \
    r0f = fminf(fmaxf(truncf(r0f), 0.0f), 255.0f); \
    r1f = fminf(fmaxf(truncf(r1f), 0.0f), 255.0f); \
    if (do_store) *reinterpret_cast<float2*>(po) = make_float2(r0f, r1f); \
    po += W; \
    xc0p = xc1p;  xc1p = pk(xv.x, xv.y);

    // Guard-free steps i = 0..89 (90 = 30*3, compile-time constant).
    // Safe: max rr = r0+89 -> rr+3 = r0+92 <= 1022 for every chunk (r0 <= 930).
#pragma unroll 3
    for (int i = 0; i < CH - 4; ++i) {
        float2 xv = nxv, yv = nyv;
        LDP(nxv, pxr)  LDP(nyv, pyr)
        pxr += W;  pyr += W;
        SCORE(xv, yv)
        STAIL(xv)
    }

    // Guarded steps: last 4 rows (bottom replication for the r0 == 930 chunk).
    const int rbase = r0 + CH - 4;
#define STEP_G(k) { \
        const int rr = rbase + (k); \
        float2 xv = nxv, yv = nyv; \
        LDP(nxv, pxr)  LDP(nyv, pyr) \
        if (rr + 4 < H) { pxr += W;  pyr += W; } \
        SCORE(xv, yv) \
        if (rr + 1 >= H) { hAn = hApp;  hBn = hBpp; }   /* A(H) := A(H-1) */ \
        STAIL(xv) }

    STEP_G(0)
    STEP_G(1)
    STEP_G(2)
    STEP_G(3)
#undef STEP_G
#undef STAIL
#undef SCORE
#undef ABROW2S
#undef HQ2S
#undef LDP
#undef LD2
}

extern "C" void kernel_launch(void* const* d_in, const int* in_sizes, int n_in,
                              void* d_out, int out_size) {
    const float* x = (const float*)d_in[0];
    const float* y = (const float*)d_in[1];
    float* out     = (float*)d_out;

    gf_kernel<<<NBLOCKS, 32 * WPB>>>(x, y, out);
}